// round 1
// baseline (speedup 1.0000x reference)
#include <cuda_runtime.h>
#include <cuda_bf16.h>

// Problem dims (fixed)
#define BATCH 8
#define NQ    2048
#define NKV   2048
#define DQ    1024
#define DKV   1024
#define HH    256

// Tile config
#define BM 64
#define BN 64
#define BK 16
#define NTHREADS 256

// Scratch (device globals — no allocation allowed)
__device__ float g_sigQ[BATCH * NQ * HH];          // sigmoid(Q)            16.8 MB
__device__ float g_expK[BATCH * NKV * HH];         // exp(K)                16.8 MB
__device__ float g_ekv [BATCH * NKV * HH];         // exp(K)*V              16.8 MB
__device__ float g_Yt  [BATCH * NQ * HH];          // sig(Q)*num/den        16.8 MB
__device__ float g_expw[(size_t)BATCH * NQ * NKV]; // exp(bias)            134.2 MB

// ---------------------------------------------------------------------------
// 1) exp(bias) elementwise, vectorized
// ---------------------------------------------------------------------------
__global__ __launch_bounds__(256) void exp_bias_kernel(const float* __restrict__ bias) {
    int i = blockIdx.x * blockDim.x + threadIdx.x;  // i indexes float4
    float4 v = reinterpret_cast<const float4*>(bias)[i];
    v.x = __expf(v.x);
    v.y = __expf(v.y);
    v.z = __expf(v.z);
    v.w = __expf(v.w);
    reinterpret_cast<float4*>(g_expw)[i] = v;
}

// ---------------------------------------------------------------------------
// 2) Q projection: sigQ = sigmoid(x_q @ wq_w + wq_b)
//    A: [16384, 1024] row-major, W: [1024, 256] row-major
// ---------------------------------------------------------------------------
__global__ __launch_bounds__(NTHREADS) void proj_q_kernel(
    const float* __restrict__ A, const float* __restrict__ W,
    const float* __restrict__ bvec)
{
    __shared__ float As[BM][BK + 1];
    __shared__ float Bs[BK][BN];

    const int tid  = threadIdx.x;
    const int brow = blockIdx.y * BM;
    const int bcol = blockIdx.x * BN;
    const int arow = tid >> 2;           // 0..63
    const int ac4  = (tid & 3) * 4;      // 0,4,8,12
    const int bkr  = tid >> 4;           // 0..15
    const int bc4  = (tid & 15) * 4;     // 0..60
    const int ty   = tid >> 4;           // 0..15
    const int tx   = tid & 15;           // 0..15

    const int K = DQ, N = HH;
    float acc[4][4] = {};

    for (int k0 = 0; k0 < K; k0 += BK) {
        float4 a = *reinterpret_cast<const float4*>(A + (size_t)(brow + arow) * K + k0 + ac4);
        As[arow][ac4 + 0] = a.x;
        As[arow][ac4 + 1] = a.y;
        As[arow][ac4 + 2] = a.z;
        As[arow][ac4 + 3] = a.w;
        *reinterpret_cast<float4*>(&Bs[bkr][bc4]) =
            *reinterpret_cast<const float4*>(W + (size_t)(k0 + bkr) * N + bcol + bc4);
        __syncthreads();
#pragma unroll
        for (int k = 0; k < BK; k++) {
            float4 b = *reinterpret_cast<const float4*>(&Bs[k][tx * 4]);
#pragma unroll
            for (int i = 0; i < 4; i++) {
                float av = As[ty * 4 + i][k];
                acc[i][0] += av * b.x;
                acc[i][1] += av * b.y;
                acc[i][2] += av * b.z;
                acc[i][3] += av * b.w;
            }
        }
        __syncthreads();
    }

#pragma unroll
    for (int i = 0; i < 4; i++) {
        int row = brow + ty * 4 + i;
#pragma unroll
        for (int j = 0; j < 4; j++) {
            int col = bcol + tx * 4 + j;
            float v = acc[i][j] + bvec[col];
            g_sigQ[(size_t)row * HH + col] = 1.0f / (1.0f + __expf(-v));
        }
    }
}

// ---------------------------------------------------------------------------
// 3) K/V projection (dual GEMM, shared A = x_kv):
//    expK = exp(x_kv @ wk_w + wk_b);  ekv = expK * (x_kv @ wv_w + wv_b)
// ---------------------------------------------------------------------------
__global__ __launch_bounds__(NTHREADS) void proj_kv_kernel(
    const float* __restrict__ A,
    const float* __restrict__ Wk, const float* __restrict__ bk,
    const float* __restrict__ Wv, const float* __restrict__ bv)
{
    __shared__ float As [BM][BK + 1];
    __shared__ float Bsk[BK][BN];
    __shared__ float Bsv[BK][BN];

    const int tid  = threadIdx.x;
    const int brow = blockIdx.y * BM;
    const int bcol = blockIdx.x * BN;
    const int arow = tid >> 2;
    const int ac4  = (tid & 3) * 4;
    const int bkr  = tid >> 4;
    const int bc4  = (tid & 15) * 4;
    const int ty   = tid >> 4;
    const int tx   = tid & 15;

    const int K = DKV, N = HH;
    float acck[4][4] = {};
    float accv[4][4] = {};

    for (int k0 = 0; k0 < K; k0 += BK) {
        float4 a = *reinterpret_cast<const float4*>(A + (size_t)(brow + arow) * K + k0 + ac4);
        As[arow][ac4 + 0] = a.x;
        As[arow][ac4 + 1] = a.y;
        As[arow][ac4 + 2] = a.z;
        As[arow][ac4 + 3] = a.w;
        *reinterpret_cast<float4*>(&Bsk[bkr][bc4]) =
            *reinterpret_cast<const float4*>(Wk + (size_t)(k0 + bkr) * N + bcol + bc4);
        *reinterpret_cast<float4*>(&Bsv[bkr][bc4]) =
            *reinterpret_cast<const float4*>(Wv + (size_t)(k0 + bkr) * N + bcol + bc4);
        __syncthreads();
#pragma unroll
        for (int k = 0; k < BK; k++) {
            float4 b1 = *reinterpret_cast<const float4*>(&Bsk[k][tx * 4]);
            float4 b2 = *reinterpret_cast<const float4*>(&Bsv[k][tx * 4]);
#pragma unroll
            for (int i = 0; i < 4; i++) {
                float av = As[ty * 4 + i][k];
                acck[i][0] += av * b1.x;
                acck[i][1] += av * b1.y;
                acck[i][2] += av * b1.z;
                acck[i][3] += av * b1.w;
                accv[i][0] += av * b2.x;
                accv[i][1] += av * b2.y;
                accv[i][2] += av * b2.z;
                accv[i][3] += av * b2.w;
            }
        }
        __syncthreads();
    }

#pragma unroll
    for (int i = 0; i < 4; i++) {
        int row = brow + ty * 4 + i;
#pragma unroll
        for (int j = 0; j < 4; j++) {
            int col = bcol + tx * 4 + j;
            float ek = __expf(acck[i][j] + bk[col]);
            float vv = accv[i][j] + bv[col];
            size_t idx = (size_t)row * HH + col;
            g_expK[idx] = ek;
            g_ekv [idx] = ek * vv;
        }
    }
}

// ---------------------------------------------------------------------------
// 4) AFT core (batched dual GEMM over exp(bias)):
//    num = expw @ ekv ; den = expw @ expK ; Yt = sigQ * num / den
// ---------------------------------------------------------------------------
__global__ __launch_bounds__(NTHREADS) void aft_core_kernel() {
    __shared__ float As [BM][BK + 1];
    __shared__ float Bs1[BK][BN];
    __shared__ float Bs2[BK][BN];

    const int z    = blockIdx.z;
    const int tid  = threadIdx.x;
    const int brow = blockIdx.y * BM;
    const int bcol = blockIdx.x * BN;
    const int arow = tid >> 2;
    const int ac4  = (tid & 3) * 4;
    const int bkr  = tid >> 4;
    const int bc4  = (tid & 15) * 4;
    const int ty   = tid >> 4;
    const int tx   = tid & 15;

    const float* A  = g_expw + (size_t)z * NQ * NKV;   // [NQ, NKV]
    const float* B1 = g_ekv  + (size_t)z * NKV * HH;   // [NKV, HH]
    const float* B2 = g_expK + (size_t)z * NKV * HH;

    const int K = NKV, N = HH;
    float acc1[4][4] = {};
    float acc2[4][4] = {};

    for (int k0 = 0; k0 < K; k0 += BK) {
        float4 a = *reinterpret_cast<const float4*>(A + (size_t)(brow + arow) * K + k0 + ac4);
        As[arow][ac4 + 0] = a.x;
        As[arow][ac4 + 1] = a.y;
        As[arow][ac4 + 2] = a.z;
        As[arow][ac4 + 3] = a.w;
        *reinterpret_cast<float4*>(&Bs1[bkr][bc4]) =
            *reinterpret_cast<const float4*>(B1 + (size_t)(k0 + bkr) * N + bcol + bc4);
        *reinterpret_cast<float4*>(&Bs2[bkr][bc4]) =
            *reinterpret_cast<const float4*>(B2 + (size_t)(k0 + bkr) * N + bcol + bc4);
        __syncthreads();
#pragma unroll
        for (int k = 0; k < BK; k++) {
            float4 b1 = *reinterpret_cast<const float4*>(&Bs1[k][tx * 4]);
            float4 b2 = *reinterpret_cast<const float4*>(&Bs2[k][tx * 4]);
#pragma unroll
            for (int i = 0; i < 4; i++) {
                float av = As[ty * 4 + i][k];
                acc1[i][0] += av * b1.x;
                acc1[i][1] += av * b1.y;
                acc1[i][2] += av * b1.z;
                acc1[i][3] += av * b1.w;
                acc2[i][0] += av * b2.x;
                acc2[i][1] += av * b2.y;
                acc2[i][2] += av * b2.z;
                acc2[i][3] += av * b2.w;
            }
        }
        __syncthreads();
    }

#pragma unroll
    for (int i = 0; i < 4; i++) {
        int row = brow + ty * 4 + i;
#pragma unroll
        for (int j = 0; j < 4; j++) {
            int col = bcol + tx * 4 + j;
            size_t idx = (size_t)z * NQ * HH + (size_t)row * HH + col;
            g_Yt[idx] = g_sigQ[idx] * (acc1[i][j] / acc2[i][j]);
        }
    }
}

// ---------------------------------------------------------------------------
// 5) Output projection: out = Yt @ f2_w + f2_b   ([16384,256] @ [256,256])
// ---------------------------------------------------------------------------
__global__ __launch_bounds__(NTHREADS) void out_proj_kernel(
    const float* __restrict__ W, const float* __restrict__ bvec,
    float* __restrict__ out)
{
    __shared__ float As[BM][BK + 1];
    __shared__ float Bs[BK][BN];

    const int tid  = threadIdx.x;
    const int brow = blockIdx.y * BM;
    const int bcol = blockIdx.x * BN;
    const int arow = tid >> 2;
    const int ac4  = (tid & 3) * 4;
    const int bkr  = tid >> 4;
    const int bc4  = (tid & 15) * 4;
    const int ty   = tid >> 4;
    const int tx   = tid & 15;

    const int K = HH, N = HH;
    const float* A = g_Yt;
    float acc[4][4] = {};

    for (int k0 = 0; k0 < K; k0 += BK) {
        float4 a = *reinterpret_cast<const float4*>(A + (size_t)(brow + arow) * K + k0 + ac4);
        As[arow][ac4 + 0] = a.x;
        As[arow][ac4 + 1] = a.y;
        As[arow][ac4 + 2] = a.z;
        As[arow][ac4 + 3] = a.w;
        *reinterpret_cast<float4*>(&Bs[bkr][bc4]) =
            *reinterpret_cast<const float4*>(W + (size_t)(k0 + bkr) * N + bcol + bc4);
        __syncthreads();
#pragma unroll
        for (int k = 0; k < BK; k++) {
            float4 b = *reinterpret_cast<const float4*>(&Bs[k][tx * 4]);
#pragma unroll
            for (int i = 0; i < 4; i++) {
                float av = As[ty * 4 + i][k];
                acc[i][0] += av * b.x;
                acc[i][1] += av * b.y;
                acc[i][2] += av * b.z;
                acc[i][3] += av * b.w;
            }
        }
        __syncthreads();
    }

#pragma unroll
    for (int i = 0; i < 4; i++) {
        int row = brow + ty * 4 + i;
#pragma unroll
        for (int j = 0; j < 4; j++) {
            int col = bcol + tx * 4 + j;
            out[(size_t)row * HH + col] = acc[i][j] + bvec[col];
        }
    }
}

// ---------------------------------------------------------------------------
// Launch
// Input order (reference signature):
//  0:x_q 1:x_kv 2:bias 3:wq_w 4:wq_b 5:wk_w 6:wk_b 7:wv_w 8:wv_b 9:f2_w 10:f2_b
// ---------------------------------------------------------------------------
extern "C" void kernel_launch(void* const* d_in, const int* in_sizes, int n_in,
                              void* d_out, int out_size) {
    (void)in_sizes; (void)n_in; (void)out_size;
    const float* x_q  = (const float*)d_in[0];
    const float* x_kv = (const float*)d_in[1];
    const float* bias = (const float*)d_in[2];
    const float* wq_w = (const float*)d_in[3];
    const float* wq_b = (const float*)d_in[4];
    const float* wk_w = (const float*)d_in[5];
    const float* wk_b = (const float*)d_in[6];
    const float* wv_w = (const float*)d_in[7];
    const float* wv_b = (const float*)d_in[8];
    const float* f2_w = (const float*)d_in[9];
    const float* f2_b = (const float*)d_in[10];
    float* out = (float*)d_out;

    // 1) exp(bias) -> g_expw
    {
        int n4 = (BATCH * NQ * NKV) / 4;
        exp_bias_kernel<<<n4 / 256, 256>>>(bias);
    }
    // 2) sigQ
    {
        dim3 grid(HH / BN, (BATCH * NQ) / BM);
        proj_q_kernel<<<grid, NTHREADS>>>(x_q, wq_w, wq_b);
    }
    // 3) expK, ekv
    {
        dim3 grid(HH / BN, (BATCH * NKV) / BM);
        proj_kv_kernel<<<grid, NTHREADS>>>(x_kv, wk_w, wk_b, wv_w, wv_b);
    }
    // 4) Yt
    {
        dim3 grid(HH / BN, NQ / BM, BATCH);
        aft_core_kernel<<<grid, NTHREADS>>>();
    }
    // 5) out
    {
        dim3 grid(HH / BN, (BATCH * NQ) / BM);
        out_proj_kernel<<<grid, NTHREADS>>>(f2_w, f2_b, out);
    }
}

// round 3
// speedup vs baseline: 1.6939x; 1.6939x over previous
#include <cuda_runtime.h>
#include <mma.h>
#include <cstdint>

using namespace nvcuda;

// Problem dims (fixed)
#define BATCH 8
#define NQ    2048
#define NKV   2048
#define DQ    1024
#define DKV   1024
#define HH    256

// GEMM tile config
#define BM 128
#define BN 128
#define BKC 32          // K chunk
#define NTHREADS 256

// Scratch (device globals — no allocation allowed)
__device__ float g_sigQ[BATCH * NQ * HH];           // sigmoid(Q)
__device__ float g_expK[BATCH * NKV * HH];          // exp(K)      [B*NKV, H] row-major
__device__ float g_ekv [BATCH * NKV * HH];          // exp(K)*V    [B*NKV, H] row-major
__device__ float g_Yt  [BATCH * NQ * HH];           // sig(Q)*num/den
__device__ float g_expw[(size_t)BATCH * NQ * NKV];  // exp(bias)   [B][NQ][NKV]

// ---------------------------------------------------------------------------
// smem layout (in floats). A tiles: 128 rows x 32 cols, pad to 40 (160B rows).
// B tiles: 32 rows x 128 cols, pad to 136 (544B rows).
// ---------------------------------------------------------------------------
#define SA_STRIDE 40
#define SB_STRIDE 136
#define SA_TILE  (BM * SA_STRIDE)        // 5120 floats
#define SB_TILE  (BKC * SB_STRIDE)       // 4352 floats
#define SA_OFF(buf)    ((buf) * SA_TILE)
#define SB_OFF(t, buf) (2 * SA_TILE + ((t) * 2 + (buf)) * SB_TILE)
#define SMEM_FLOATS(NB) (2 * SA_TILE + (NB) * 2 * SB_TILE)
// epilogue staging: per-warp 32 x 72 floats
#define STG_STRIDE 72
#define STG_WARP  (32 * STG_STRIDE)      // 2304 floats (73728 B total < mainloop smem)

__device__ __forceinline__ void cp16(uint32_t saddr, const void* gptr) {
    asm volatile("cp.async.cg.shared.global [%0], [%1], 16;" :: "r"(saddr), "l"(gptr));
}
#define CP_COMMIT() asm volatile("cp.async.commit_group;" ::: "memory")

// ---------------------------------------------------------------------------
// 1) exp(bias) elementwise
// ---------------------------------------------------------------------------
__global__ __launch_bounds__(256) void exp_bias_kernel(const float* __restrict__ bias) {
    int i = blockIdx.x * blockDim.x + threadIdx.x;  // float4 index
    float4 v = reinterpret_cast<const float4*>(bias)[i];
    v.x = __expf(v.x); v.y = __expf(v.y); v.z = __expf(v.z); v.w = __expf(v.w);
    reinterpret_cast<float4*>(g_expw)[i] = v;
}

// ---------------------------------------------------------------------------
// Unified tf32 wmma GEMM (row-major A, row-major B), single or dual B,
// fused epilogues. C tile = 128x128, 8 warps as 4x2 (warp tile 32x64).
// EPI: 0 = sigmoid(A@B0 + v0)            -> O0
//      1 = ek=exp(A@B0+v0); O0=ek; O1=ek*(A@B1+v1)
//      2 = O0 = aux * (A@B0) / (A@B1)
//      3 = O0 = A@B0 + v0
// ---------------------------------------------------------------------------
template<int NB, int EPI>
__global__ __launch_bounds__(NTHREADS, 1) void gemm_tc_kernel(
    const float* __restrict__ A, unsigned long long strideAz, int lda,
    const float* __restrict__ B0g, const float* __restrict__ B1g,
    unsigned long long strideBz, int Ktot,
    const float* __restrict__ v0, const float* __restrict__ v1,
    const float* __restrict__ aux, unsigned long long strideXz,
    float* __restrict__ O0, float* __restrict__ O1, unsigned long long strideOz)
{
    extern __shared__ __align__(16) float sm[];
    const int tid  = threadIdx.x;
    const int wid  = tid >> 5;
    const int lane = tid & 31;
    const int m0 = blockIdx.x * BM;
    const int n0 = blockIdx.y * BN;
    const int z  = blockIdx.z;
    const int wm = wid >> 1;      // 0..3
    const int wn = wid & 1;       // 0..1

    const float* Ab = A + (size_t)z * strideAz + (size_t)m0 * lda;
    const float* Bb[2];
    Bb[0] = B0g + (size_t)z * strideBz;
    if (NB > 1) Bb[1] = B1g + (size_t)z * strideBz;

    using FragA = wmma::fragment<wmma::matrix_a, 16, 16, 8, wmma::precision::tf32, wmma::row_major>;
    using FragB = wmma::fragment<wmma::matrix_b, 16, 16, 8, wmma::precision::tf32, wmma::row_major>;
    using FragC = wmma::fragment<wmma::accumulator, 16, 16, 8, float>;

    FragC acc[NB][2][4];
#pragma unroll
    for (int t = 0; t < NB; t++)
#pragma unroll
        for (int mi = 0; mi < 2; mi++)
#pragma unroll
            for (int ni = 0; ni < 4; ni++)
                wmma::fill_fragment(acc[t][mi][ni], 0.0f);

    auto load_chunk = [&](int buf, int k0) {
        // A tile: 128 x 32 floats = 1024 float4, 4 per thread
#pragma unroll
        for (int i = 0; i < 4; i++) {
            int idx = tid + i * 256;
            int r = idx >> 3, c4 = idx & 7;
            uint32_t s = (uint32_t)__cvta_generic_to_shared(
                sm + SA_OFF(buf) + r * SA_STRIDE + c4 * 4);
            cp16(s, Ab + (size_t)r * lda + k0 + c4 * 4);
        }
        // B tiles: 32 x 128 floats each
#pragma unroll
        for (int t = 0; t < NB; t++)
#pragma unroll
            for (int i = 0; i < 4; i++) {
                int idx = tid + i * 256;
                int r = idx >> 5, c4 = idx & 31;
                uint32_t s = (uint32_t)__cvta_generic_to_shared(
                    sm + SB_OFF(t, buf) + r * SB_STRIDE + c4 * 4);
                cp16(s, Bb[t] + (size_t)(k0 + r) * HH + n0 + c4 * 4);
            }
        CP_COMMIT();
    };

    load_chunk(0, 0);
    const int nchunk = Ktot / BKC;

    for (int c = 0; c < nchunk; c++) {
        const int buf = c & 1;
        if (c + 1 < nchunk) {
            load_chunk(buf ^ 1, (c + 1) * BKC);
            asm volatile("cp.async.wait_group 1;" ::: "memory");
        } else {
            asm volatile("cp.async.wait_group 0;" ::: "memory");
        }
        __syncthreads();
#pragma unroll
        for (int kk = 0; kk < 4; kk++) {
            FragA a[2];
#pragma unroll
            for (int mi = 0; mi < 2; mi++) {
                wmma::load_matrix_sync(a[mi],
                    sm + SA_OFF(buf) + (wm * 32 + mi * 16) * SA_STRIDE + kk * 8, SA_STRIDE);
#pragma unroll
                for (int e = 0; e < a[mi].num_elements; e++)
                    a[mi].x[e] = wmma::__float_to_tf32(a[mi].x[e]);
            }
#pragma unroll
            for (int t = 0; t < NB; t++) {
#pragma unroll
                for (int ni = 0; ni < 4; ni++) {
                    FragB b;
                    wmma::load_matrix_sync(b,
                        sm + SB_OFF(t, buf) + kk * 8 * SB_STRIDE + wn * 64 + ni * 16, SB_STRIDE);
#pragma unroll
                    for (int e = 0; e < b.num_elements; e++)
                        b.x[e] = wmma::__float_to_tf32(b.x[e]);
#pragma unroll
                    for (int mi = 0; mi < 2; mi++)
                        wmma::mma_sync(acc[t][mi][ni], a[mi], b, acc[t][mi][ni]);
                }
            }
        }
        __syncthreads();
    }

    // ------------------- Epilogue (per-warp staging in smem) -----------------
    float* stage = sm + wid * STG_WARP;

    float r0[64];
#pragma unroll
    for (int mi = 0; mi < 2; mi++)
#pragma unroll
        for (int ni = 0; ni < 4; ni++)
            wmma::store_matrix_sync(stage + mi * 16 * STG_STRIDE + ni * 16,
                                    acc[0][mi][ni], STG_STRIDE, wmma::mem_row_major);
    __syncwarp();
#pragma unroll
    for (int s = 0; s < 16; s++) {
        int fi = s * 32 + lane;
        int r = fi >> 4, c4 = fi & 15;
        float4 v = *reinterpret_cast<float4*>(stage + r * STG_STRIDE + c4 * 4);
        r0[s * 4 + 0] = v.x; r0[s * 4 + 1] = v.y; r0[s * 4 + 2] = v.z; r0[s * 4 + 3] = v.w;
    }

    float r1[64];
    if (NB > 1) {
        __syncwarp();
#pragma unroll
        for (int mi = 0; mi < 2; mi++)
#pragma unroll
            for (int ni = 0; ni < 4; ni++)
                wmma::store_matrix_sync(stage + mi * 16 * STG_STRIDE + ni * 16,
                                        acc[1][mi][ni], STG_STRIDE, wmma::mem_row_major);
        __syncwarp();
#pragma unroll
        for (int s = 0; s < 16; s++) {
            int fi = s * 32 + lane;
            int r = fi >> 4, c4 = fi & 15;
            float4 v = *reinterpret_cast<float4*>(stage + r * STG_STRIDE + c4 * 4);
            r1[s * 4 + 0] = v.x; r1[s * 4 + 1] = v.y; r1[s * 4 + 2] = v.z; r1[s * 4 + 3] = v.w;
        }
    }

#pragma unroll
    for (int s = 0; s < 16; s++) {
        int fi = s * 32 + lane;
        int r = fi >> 4, c4 = fi & 15;
        int grow = m0 + wm * 32 + r;
        int gcol = n0 + wn * 64 + c4 * 4;
        size_t o = (size_t)z * strideOz + (size_t)grow * HH + gcol;

        if (EPI == 0) {         // sigmoid(x + bias)
            float4 bv = *reinterpret_cast<const float4*>(v0 + gcol);
            float4 ov;
            ov.x = 1.0f / (1.0f + __expf(-(r0[s * 4 + 0] + bv.x)));
            ov.y = 1.0f / (1.0f + __expf(-(r0[s * 4 + 1] + bv.y)));
            ov.z = 1.0f / (1.0f + __expf(-(r0[s * 4 + 2] + bv.z)));
            ov.w = 1.0f / (1.0f + __expf(-(r0[s * 4 + 3] + bv.w)));
            *reinterpret_cast<float4*>(O0 + o) = ov;
        } else if (EPI == 1) {  // expK / ekv
            float4 bk = *reinterpret_cast<const float4*>(v0 + gcol);
            float4 bb = *reinterpret_cast<const float4*>(v1 + gcol);
            float4 ek, kv;
            ek.x = __expf(r0[s * 4 + 0] + bk.x); kv.x = ek.x * (r1[s * 4 + 0] + bb.x);
            ek.y = __expf(r0[s * 4 + 1] + bk.y); kv.y = ek.y * (r1[s * 4 + 1] + bb.y);
            ek.z = __expf(r0[s * 4 + 2] + bk.z); kv.z = ek.z * (r1[s * 4 + 2] + bb.z);
            ek.w = __expf(r0[s * 4 + 3] + bk.w); kv.w = ek.w * (r1[s * 4 + 3] + bb.w);
            *reinterpret_cast<float4*>(O0 + o) = ek;
            *reinterpret_cast<float4*>(O1 + o) = kv;
        } else if (EPI == 2) {  // Yt = sigQ * num / den
            float4 sq = *reinterpret_cast<const float4*>(
                aux + (size_t)z * strideXz + (size_t)grow * HH + gcol);
            float4 ov;
            ov.x = sq.x * __fdividef(r0[s * 4 + 0], r1[s * 4 + 0]);
            ov.y = sq.y * __fdividef(r0[s * 4 + 1], r1[s * 4 + 1]);
            ov.z = sq.z * __fdividef(r0[s * 4 + 2], r1[s * 4 + 2]);
            ov.w = sq.w * __fdividef(r0[s * 4 + 3], r1[s * 4 + 3]);
            *reinterpret_cast<float4*>(O0 + o) = ov;
        } else {                // out = x + bias
            float4 bv = *reinterpret_cast<const float4*>(v0 + gcol);
            float4 ov;
            ov.x = r0[s * 4 + 0] + bv.x;
            ov.y = r0[s * 4 + 1] + bv.y;
            ov.z = r0[s * 4 + 2] + bv.z;
            ov.w = r0[s * 4 + 3] + bv.w;
            *reinterpret_cast<float4*>(O0 + o) = ov;
        }
    }
}

// ---------------------------------------------------------------------------
// Launch.  Inputs (metadata order):
//  0:x_q 1:x_kv 2:bias 3:wq_w 4:wq_b 5:wk_w 6:wk_b 7:wv_w 8:wv_b 9:f2_w 10:f2_b
// ---------------------------------------------------------------------------
extern "C" void kernel_launch(void* const* d_in, const int* in_sizes, int n_in,
                              void* d_out, int out_size) {
    (void)in_sizes; (void)n_in; (void)out_size;
    const float* x_q  = (const float*)d_in[0];
    const float* x_kv = (const float*)d_in[1];
    const float* bias = (const float*)d_in[2];
    const float* wq_w = (const float*)d_in[3];
    const float* wq_b = (const float*)d_in[4];
    const float* wk_w = (const float*)d_in[5];
    const float* wk_b = (const float*)d_in[6];
    const float* wv_w = (const float*)d_in[7];
    const float* wv_b = (const float*)d_in[8];
    const float* f2_w = (const float*)d_in[9];
    const float* f2_b = (const float*)d_in[10];
    float* out = (float*)d_out;

    // Resolve device-global scratch addresses (host-side symbol lookup; no alloc)
    float *p_sigQ, *p_expK, *p_ekv, *p_Yt, *p_expw;
    cudaGetSymbolAddress((void**)&p_sigQ, g_sigQ);
    cudaGetSymbolAddress((void**)&p_expK, g_expK);
    cudaGetSymbolAddress((void**)&p_ekv,  g_ekv);
    cudaGetSymbolAddress((void**)&p_Yt,   g_Yt);
    cudaGetSymbolAddress((void**)&p_expw, g_expw);

    const int smem1 = SMEM_FLOATS(1) * 4;   // 75776 B
    const int smem2 = SMEM_FLOATS(2) * 4;   // 110592 B
    cudaFuncSetAttribute(gemm_tc_kernel<1, 0>, cudaFuncAttributeMaxDynamicSharedMemorySize, smem1);
    cudaFuncSetAttribute(gemm_tc_kernel<2, 1>, cudaFuncAttributeMaxDynamicSharedMemorySize, smem2);
    cudaFuncSetAttribute(gemm_tc_kernel<2, 2>, cudaFuncAttributeMaxDynamicSharedMemorySize, smem2);
    cudaFuncSetAttribute(gemm_tc_kernel<1, 3>, cudaFuncAttributeMaxDynamicSharedMemorySize, smem1);

    // 1) exp(bias) -> g_expw
    {
        int n4 = (int)(((size_t)BATCH * NQ * NKV) / 4);
        exp_bias_kernel<<<n4 / 256, 256>>>(bias);
    }
    // 2) sigQ = sigmoid(x_q @ wq_w + wq_b)
    {
        dim3 grid((BATCH * NQ) / BM, HH / BN, 1);
        gemm_tc_kernel<1, 0><<<grid, NTHREADS, smem1>>>(
            x_q, 0ull, DQ, wq_w, nullptr, 0ull, DQ,
            wq_b, nullptr, nullptr, 0ull, p_sigQ, nullptr, 0ull);
    }
    // 3) expK = exp(x_kv@wk+bk); ekv = expK*(x_kv@wv+bv)
    {
        dim3 grid((BATCH * NKV) / BM, HH / BN, 1);
        gemm_tc_kernel<2, 1><<<grid, NTHREADS, smem2>>>(
            x_kv, 0ull, DKV, wk_w, wv_w, 0ull, DKV,
            wk_b, wv_b, nullptr, 0ull, p_expK, p_ekv, 0ull);
    }
    // 4) Yt = sigQ * (expw@ekv) / (expw@expK), batched over z
    {
        dim3 grid(NQ / BM, HH / BN, BATCH);
        gemm_tc_kernel<2, 2><<<grid, NTHREADS, smem2>>>(
            p_expw, (unsigned long long)NQ * NKV, NKV,
            p_ekv, p_expK, (unsigned long long)NKV * HH, NKV,
            nullptr, nullptr, p_sigQ, (unsigned long long)NQ * HH,
            p_Yt, nullptr, (unsigned long long)NQ * HH);
    }
    // 5) out = Yt @ f2_w + f2_b
    {
        dim3 grid((BATCH * NQ) / BM, HH / BN, 1);
        gemm_tc_kernel<1, 3><<<grid, NTHREADS, smem1>>>(
            p_Yt, 0ull, HH, f2_w, nullptr, 0ull, HH,
            f2_b, nullptr, nullptr, 0ull, out, nullptr, 0ull);
    }
}